// round 7
// baseline (speedup 1.0000x reference)
#include <cuda_runtime.h>
#include <cuda_bf16.h>
#include <math.h>
#include <stdint.h>

#define NROWS 8192
#define DDIM  512
#define EPS   1e-5f

// ================= PTX helpers (sm_103 base-target safe: no tcgen05) =================
__device__ __forceinline__ uint32_t smem_u32(const void* p) {
    uint32_t a;
    asm("{ .reg .u64 t; cvta.to.shared.u64 t, %1; cvt.u32.u64 %0, t; }" : "=r"(a) : "l"(p));
    return a;
}
#define CP_ASYNC16(smem, gptr) \
    asm volatile("cp.async.cg.shared.global [%0], [%1], 16;" :: "r"(smem), "l"(gptr))
#define CP_COMMIT() asm volatile("cp.async.commit_group;" ::: "memory")
#define CP_WAIT(n)  asm volatile("cp.async.wait_group %0;" :: "n"(n) : "memory")

#define LDMX4(r, addr) \
    asm volatile("ldmatrix.sync.aligned.m8n8.x4.shared.b16 {%0,%1,%2,%3}, [%4];" \
        : "=r"((r)[0]), "=r"((r)[1]), "=r"((r)[2]), "=r"((r)[3]) : "r"(addr))

#define MMA16816(d, a, b0, b1) \
    asm volatile("mma.sync.aligned.m16n8k16.row.col.f32.bf16.bf16.f32 " \
        "{%0,%1,%2,%3}, {%4,%5,%6,%7}, {%8,%9}, {%0,%1,%2,%3};" \
        : "+f"((d)[0]), "+f"((d)[1]), "+f"((d)[2]), "+f"((d)[3]) \
        : "r"((a)[0]), "r"((a)[1]), "r"((a)[2]), "r"((a)[3]), "r"(b0), "r"(b1))

// ================= scratch =================
__device__ float g_q  [NROWS * DDIM];
__device__ float g_k  [NROWS * DDIM];
__device__ __nv_bfloat16 g_sh1[NROWS * DDIM];
__device__ __nv_bfloat16 g_sl1[NROWS * DDIM];
__device__ __nv_bfloat16 g_sh2[NROWS * DDIM];
__device__ __nv_bfloat16 g_sl2[NROWS * DDIM];
__device__ __nv_bfloat16 g_wh[4][DDIM * DDIM];
__device__ __nv_bfloat16 g_wl[4][DDIM * DDIM];
__device__ int   g_segs[NROWS];
__device__ int   g_sege[NROWS];

// ================= reductions =================
__device__ __forceinline__ float warpSum(float v) {
    #pragma unroll
    for (int o = 16; o > 0; o >>= 1) v += __shfl_xor_sync(0xffffffffu, v, o);
    return v;
}

// ================= segments (single kernel; reads batch directly) =================
// int64 vs int32 batch detection: for little-endian int64, the int32 word at
// index NROWS-1 is the HIGH word of element (NROWS/2-1) -> 0. For sorted int32
// it's the max batch id (>0).
__global__ void seg_kernel(const int* __restrict__ p) {
    int i = blockIdx.x * blockDim.x + threadIdx.x;
    if (i >= NROWS) return;
    const int is64 = (__ldg(p + (NROWS - 1)) == 0);
    #define GETB(idx) (is64 ? __ldg(p + 2 * (idx)) : __ldg(p + (idx)))
    int v = GETB(i);
    int lo = 0, hi = NROWS;
    while (lo < hi) { int mid = (lo + hi) >> 1; if (GETB(mid) < v) lo = mid + 1; else hi = mid; }
    g_segs[i] = lo;
    lo = 0; hi = NROWS;
    while (lo < hi) { int mid = (lo + hi) >> 1; if (GETB(mid) <= v) lo = mid + 1; else hi = mid; }
    g_sege[i] = lo;
    #undef GETB
}

// ================= split helpers =================
__device__ __forceinline__ void split2(float v, __nv_bfloat16& hi, __nv_bfloat16& lo) {
    hi = __float2bfloat16(v);
    lo = __float2bfloat16(v - __bfloat162float(hi));
}

__global__ __launch_bounds__(256) void w_split_all(const float* __restrict__ W1,
                                                   const float* __restrict__ W2,
                                                   const float* __restrict__ W3,
                                                   const float* __restrict__ W4,
                                                   __nv_bfloat16* __restrict__ wh,
                                                   __nv_bfloat16* __restrict__ wl) {
    int id = blockIdx.x * 256 + threadIdx.x;
    int w = id >> 16;
    int j = id & 65535;
    const float* src = (w == 0) ? W1 : (w == 1) ? W2 : (w == 2) ? W3 : W4;
    float4 v = ((const float4*)src)[j];
    __nv_bfloat16 h0, l0, h1, l1, h2, l2, h3, l3;
    split2(v.x, h0, l0); split2(v.y, h1, l1);
    split2(v.z, h2, l2); split2(v.w, h3, l3);
    size_t base = (size_t)w * DDIM * DDIM + (size_t)j * 4;
    __nv_bfloat162* ph = (__nv_bfloat162*)(wh + base);
    __nv_bfloat162* pl = (__nv_bfloat162*)(wl + base);
    ph[0] = __nv_bfloat162(h0, h1); ph[1] = __nv_bfloat162(h2, h3);
    pl[0] = __nv_bfloat162(l0, l1); pl[1] = __nv_bfloat162(l2, l3);
}

// ================= LayerNorm: 2 rows/block, float4, 4-warp reduction =================
__global__ __launch_bounds__(256) void ln_split_kernel(const float* __restrict__ x,
                                                       const float* __restrict__ w,
                                                       const float* __restrict__ b,
                                                       __nv_bfloat16* __restrict__ sh_,
                                                       __nv_bfloat16* __restrict__ sl_) {
    __shared__ float red[2][4];
    const int half = threadIdx.x >> 7;
    const int t    = threadIdx.x & 127;
    const int lane = threadIdx.x & 31;
    const int w4   = (threadIdx.x >> 5) & 3;
    const int row  = blockIdx.x * 2 + half;
    float4 v = ((const float4*)(x + (size_t)row * DDIM))[t];
    float ps = warpSum(v.x + v.y + v.z + v.w);
    if (lane == 0) red[half][w4] = ps;
    __syncthreads();
    float mu = (red[half][0] + red[half][1] + red[half][2] + red[half][3]) * (1.0f / DDIM);
    __syncthreads();
    float dx = v.x - mu, dy = v.y - mu, dz = v.z - mu, dw = v.w - mu;
    float pv = warpSum(dx * dx + dy * dy + dz * dz + dw * dw);
    if (lane == 0) red[half][w4] = pv;
    __syncthreads();
    float var = (red[half][0] + red[half][1] + red[half][2] + red[half][3]) * (1.0f / DDIM);
    float r = rsqrtf(var + EPS);
    float4 wv = ((const float4*)w)[t];
    float4 bv = ((const float4*)b)[t];
    float y0 = dx * r * wv.x + bv.x;
    float y1 = dy * r * wv.y + bv.y;
    float y2 = dz * r * wv.z + bv.z;
    float y3 = dw * r * wv.w + bv.w;
    __nv_bfloat16 h0, l0, h1, l1, h2, l2, h3, l3;
    split2(y0, h0, l0); split2(y1, h1, l1);
    split2(y2, h2, l2); split2(y3, h3, l3);
    size_t o = (size_t)row * DDIM + t * 4;
    __nv_bfloat162* ph = (__nv_bfloat162*)(sh_ + o);
    __nv_bfloat162* pl = (__nv_bfloat162*)(sl_ + o);
    ph[0] = __nv_bfloat162(h0, h1); ph[1] = __nv_bfloat162(h2, h3);
    pl[0] = __nv_bfloat162(l0, l1); pl[1] = __nv_bfloat162(l2, l3);
}

__global__ __launch_bounds__(256) void ln_kernel(const float* __restrict__ x,
                                                 const float* __restrict__ w,
                                                 const float* __restrict__ b,
                                                 float* __restrict__ y) {
    __shared__ float red[2][4];
    const int half = threadIdx.x >> 7;
    const int t    = threadIdx.x & 127;
    const int lane = threadIdx.x & 31;
    const int w4   = (threadIdx.x >> 5) & 3;
    const int row  = blockIdx.x * 2 + half;
    float4 v = ((const float4*)(x + (size_t)row * DDIM))[t];
    float ps = warpSum(v.x + v.y + v.z + v.w);
    if (lane == 0) red[half][w4] = ps;
    __syncthreads();
    float mu = (red[half][0] + red[half][1] + red[half][2] + red[half][3]) * (1.0f / DDIM);
    __syncthreads();
    float dx = v.x - mu, dy = v.y - mu, dz = v.z - mu, dw = v.w - mu;
    float pv = warpSum(dx * dx + dy * dy + dz * dz + dw * dw);
    if (lane == 0) red[half][w4] = pv;
    __syncthreads();
    float var = (red[half][0] + red[half][1] + red[half][2] + red[half][3]) * (1.0f / DDIM);
    float r = rsqrtf(var + EPS);
    float4 wv = ((const float4*)w)[t];
    float4 bv = ((const float4*)b)[t];
    float4 o;
    o.x = dx * r * wv.x + bv.x;
    o.y = dy * r * wv.y + bv.y;
    o.z = dz * r * wv.z + bv.z;
    o.w = dw * r * wv.w + bv.w;
    ((float4*)(y + (size_t)row * DDIM))[t] = o;
}

// ================= mma.sync bf16-split GEMM =================
// BM=128, BN=128, BK=32, 8 warps, 3-stage cp.async pipeline, swizzled 64B rows.
// __launch_bounds__(256,2): 2 CTAs/SM (192KB smem), 256-CTA grid = ONE wave.
#define GM_STAGE 32768
#define GM_SMEM  (3 * GM_STAGE)

__device__ __forceinline__ uint32_t swz(int row, int c16) {
    return (uint32_t)(row * 64 + ((c16 ^ ((row >> 1) & 3)) << 4));
}

__global__ __launch_bounds__(256, 2) void gemm_mma(const __nv_bfloat16* __restrict__ Ah,
                                                   const __nv_bfloat16* __restrict__ Al,
                                                   const __nv_bfloat16* __restrict__ Bh,
                                                   const __nv_bfloat16* __restrict__ Bl,
                                                   float* __restrict__ C) {
    extern __shared__ char smem[];
    const uint32_t sbase = smem_u32(smem);
    const int tid  = threadIdx.x;
    const int lane = tid & 31;
    const int wid  = tid >> 5;
    const int wm   = wid >> 1;
    const int wn   = wid & 1;
    const int bm   = blockIdx.y * 128;
    const int bn   = blockIdx.x * 128;

    float acc[2][8][4];
    #pragma unroll
    for (int mi = 0; mi < 2; mi++)
        #pragma unroll
        for (int nj = 0; nj < 8; nj++)
            #pragma unroll
            for (int c = 0; c < 4; c++) acc[mi][nj][c] = 0.0f;

    const int id0 = tid, id1 = tid + 256;
    const int lr0 = id0 >> 2, lc0 = id0 & 3;
    const int lr1 = id1 >> 2, lc1 = id1 & 3;
    const uint32_t so0 = swz(lr0, lc0), so1 = swz(lr1, lc1);

    const int arow = (lane & 15);
    const int acol = (lane >> 4);
    const int brow = (lane & 7) + ((lane >> 4) & 1) * 8;
    const int bcol = (lane >> 3) & 1;

    #define GM_ISSUE(st, kt) do { \
        uint32_t sb_ = sbase + (st) * GM_STAGE; \
        int k0_ = (kt) * 32; \
        size_t ga0 = (size_t)(bm + lr0) * DDIM + k0_ + lc0 * 8; \
        size_t gb0 = (size_t)(bn + lr0) * DDIM + k0_ + lc0 * 8; \
        size_t ga1 = (size_t)(bm + lr1) * DDIM + k0_ + lc1 * 8; \
        size_t gb1 = (size_t)(bn + lr1) * DDIM + k0_ + lc1 * 8; \
        CP_ASYNC16(sb_ + so0,         Ah + ga0); \
        CP_ASYNC16(sb_ + 8192 + so0,  Al + ga0); \
        CP_ASYNC16(sb_ + 16384 + so0, Bh + gb0); \
        CP_ASYNC16(sb_ + 24576 + so0, Bl + gb0); \
        CP_ASYNC16(sb_ + so1,         Ah + ga1); \
        CP_ASYNC16(sb_ + 8192 + so1,  Al + ga1); \
        CP_ASYNC16(sb_ + 16384 + so1, Bh + gb1); \
        CP_ASYNC16(sb_ + 24576 + so1, Bl + gb1); \
    } while (0)

    GM_ISSUE(0, 0); CP_COMMIT();
    GM_ISSUE(1, 1); CP_COMMIT();

    for (int kt = 0; kt < 16; kt++) {
        if (kt < 14) CP_WAIT(1); else CP_WAIT(0);
        __syncthreads();
        const uint32_t sb = sbase + (kt % 3) * GM_STAGE;

        #pragma unroll
        for (int ks = 0; ks < 2; ks++) {
            uint32_t fah[2][4], fal[2][4];
            #pragma unroll
            for (int mi = 0; mi < 2; mi++) {
                uint32_t off = swz(wm * 32 + mi * 16 + arow, ks * 2 + acol);
                LDMX4(fah[mi], sb + off);
                LDMX4(fal[mi], sb + 8192 + off);
            }
            #pragma unroll
            for (int njp = 0; njp < 8; njp += 2) {
                uint32_t off = swz(wn * 64 + njp * 8 + brow, ks * 2 + bcol);
                uint32_t fbh[4], fbl[4];
                LDMX4(fbh, sb + 16384 + off);
                LDMX4(fbl, sb + 24576 + off);
                #pragma unroll
                for (int mi = 0; mi < 2; mi++) {
                    MMA16816(acc[mi][njp],     fah[mi], fbh[0], fbh[1]);
                    MMA16816(acc[mi][njp + 1], fah[mi], fbh[2], fbh[3]);
                    MMA16816(acc[mi][njp],     fah[mi], fbl[0], fbl[1]);
                    MMA16816(acc[mi][njp + 1], fah[mi], fbl[2], fbl[3]);
                    MMA16816(acc[mi][njp],     fal[mi], fbh[0], fbh[1]);
                    MMA16816(acc[mi][njp + 1], fal[mi], fbh[2], fbh[3]);
                }
            }
        }
        if (kt + 2 < 16) { GM_ISSUE((kt + 2) % 3, kt + 2); CP_COMMIT(); }
    }

    const int erow = lane >> 2;
    const int ecol = (lane & 3) * 2;
    #pragma unroll
    for (int mi = 0; mi < 2; mi++) {
        #pragma unroll
        for (int nj = 0; nj < 8; nj++) {
            int m0 = bm + wm * 32 + mi * 16 + erow;
            int n0 = bn + wn * 64 + nj * 8 + ecol;
            float2 v0 = make_float2(acc[mi][nj][0], acc[mi][nj][1]);
            float2 v1 = make_float2(acc[mi][nj][2], acc[mi][nj][3]);
            *(float2*)(C + (size_t)m0 * DDIM + n0)       = v0;
            *(float2*)(C + (size_t)(m0 + 8) * DDIM + n0) = v1;
        }
    }
}

// ================= GEMM epilogues =================
__global__ __launch_bounds__(256) void epi_silu_split(const float* __restrict__ C,
                                                      const float* __restrict__ bias,
                                                      __nv_bfloat16* __restrict__ sh_,
                                                      __nv_bfloat16* __restrict__ sl_) {
    int i = blockIdx.x * 256 + threadIdx.x;
    float v = C[i] + bias[i & (DDIM - 1)];
    v = v / (1.0f + expf(-v));
    __nv_bfloat16 h, l;
    split2(v, h, l);
    sh_[i] = h; sl_[i] = l;
}
__global__ __launch_bounds__(256) void epi_silu_inplace(float* __restrict__ C,
                                                        const float* __restrict__ bias) {
    int i = blockIdx.x * 256 + threadIdx.x;
    float v = C[i] + bias[i & (DDIM - 1)];
    C[i] = v / (1.0f + expf(-v));
}

// ================= tiled attention =================
#define AT_TILE  32
#define AT_SMEM  (AT_TILE * DDIM * 4)

__global__ __launch_bounds__(512) void attn_softmax16(const float* __restrict__ q,
                                                      const float* __restrict__ kmat,
                                                      float* __restrict__ attn) {
    extern __shared__ float ktile[];
    const int tid = threadIdx.x, wid = tid >> 5, lane = tid & 31;
    const int i = blockIdx.x * 16 + wid;
    const int s = g_segs[i], e = g_sege[i];
    const int sb = g_segs[blockIdx.x * 16];
    const int eb = g_sege[blockIdx.x * 16 + 15];

    const float* qr = q + (size_t)i * DDIM;
    float4 qv[4];
    #pragma unroll
    for (int c = 0; c < 4; c++) qv[c] = *(const float4*)(qr + c * 128 + lane * 4);

    float* row = attn + (size_t)i * NROWS;
    float m = 0.0f;

    for (int t = sb; t < eb; t += AT_TILE) {
        const int tn = min(AT_TILE, eb - t);
        __syncthreads();
        for (int idx = tid; idx < tn * 128; idx += 512) {
            int r = idx >> 7, c = idx & 127;
            *(float4*)(ktile + r * DDIM + c * 4) = *(const float4*)(kmat + (size_t)(t + r) * DDIM + c * 4);
        }
        __syncthreads();
        const int j0 = max(s, t), j1 = min(e, t + tn);
        for (int j = j0; j < j1; j++) {
            const float* kr = ktile + (j - t) * DDIM;
            float4 k0 = *(const float4*)(kr + 0 * 128 + lane * 4);
            float4 k1 = *(const float4*)(kr + 1 * 128 + lane * 4);
            float4 k2 = *(const float4*)(kr + 2 * 128 + lane * 4);
            float4 k3 = *(const float4*)(kr + 3 * 128 + lane * 4);
            float d = qv[0].x * k0.x;
            d = fmaf(qv[0].y, k0.y, d); d = fmaf(qv[0].z, k0.z, d); d = fmaf(qv[0].w, k0.w, d);
            d = fmaf(qv[1].x, k1.x, d); d = fmaf(qv[1].y, k1.y, d); d = fmaf(qv[1].z, k1.z, d); d = fmaf(qv[1].w, k1.w, d);
            d = fmaf(qv[2].x, k2.x, d); d = fmaf(qv[2].y, k2.y, d); d = fmaf(qv[2].z, k2.z, d); d = fmaf(qv[2].w, k2.w, d);
            d = fmaf(qv[3].x, k3.x, d); d = fmaf(qv[3].y, k3.y, d); d = fmaf(qv[3].z, k3.z, d); d = fmaf(qv[3].w, k3.w, d);
            d = warpSum(d);
            if (lane == 0) row[j] = d;
            m = fmaxf(m, d);
        }
    }
    m = fmaxf(m, 0.0f);   // reference: max over dot*mask includes zeros

    float ssum = 0.0f;
    for (int j = s + lane; j < e; j += 32) {
        float ev = expf(row[j] - m);
        ssum += ev;
        row[j] = ev;
    }
    ssum = warpSum(ssum);
    float inv = 1.0f / ssum;
    for (int j = s + lane; j < e; j += 32) row[j] *= inv;
}

__global__ __launch_bounds__(512) void attn_apply16(const float* __restrict__ attn,
                                                    const float* __restrict__ xc,
                                                    __nv_bfloat16* __restrict__ sh_,
                                                    __nv_bfloat16* __restrict__ sl_) {
    extern __shared__ float xtile[];
    const int tid = threadIdx.x, wid = tid >> 5, lane = tid & 31;
    const int i = blockIdx.x * 16 + wid;
    const int s = g_segs[i], e = g_sege[i];
    const int sb = g_segs[blockIdx.x * 16];
    const int eb = g_sege[blockIdx.x * 16 + 15];
    const float* row = attn + (size_t)i * NROWS;

    float4 acc[4];
    #pragma unroll
    for (int c = 0; c < 4; c++) acc[c] = make_float4(0.f, 0.f, 0.f, 0.f);

    for (int t = sb; t < eb; t += AT_TILE) {
        const int tn = min(AT_TILE, eb - t);
        __syncthreads();
        for (int idx = tid; idx < tn * 128; idx += 512) {
            int r = idx >> 7, c = idx & 127;
            *(float4*)(xtile + r * DDIM + c * 4) = *(const float4*)(xc + (size_t)(t + r) * DDIM + c * 4);
        }
        __syncthreads();
        const int j0 = max(s, t), j1 = min(e, t + tn);
        for (int j = j0; j < j1; j++) {
            float a = __ldg(row + j);
            const float* xr = xtile + (j - t) * DDIM;
            #pragma unroll
            for (int c = 0; c < 4; c++) {
                float4 v = *(const float4*)(xr + c * 128 + lane * 4);
                acc[c].x = fmaf(a, v.x, acc[c].x);
                acc[c].y = fmaf(a, v.y, acc[c].y);
                acc[c].z = fmaf(a, v.z, acc[c].z);
                acc[c].w = fmaf(a, v.w, acc[c].w);
            }
        }
    }

    size_t base = (size_t)i * DDIM;
    #pragma unroll
    for (int c = 0; c < 4; c++) {
        size_t o = base + c * 128 + lane * 4;
        __nv_bfloat16 h, l;
        split2(acc[c].x, h, l); sh_[o + 0] = h; sl_[o + 0] = l;
        split2(acc[c].y, h, l); sh_[o + 1] = h; sl_[o + 1] = l;
        split2(acc[c].z, h, l); sh_[o + 2] = h; sl_[o + 2] = l;
        split2(acc[c].w, h, l); sh_[o + 3] = h; sl_[o + 3] = l;
    }
}

// ================= launch =================
extern "C" void kernel_launch(void* const* d_in, const int* in_sizes, int n_in,
                              void* d_out, int out_size) {
    const float* x_mole  = (const float*)d_in[0];
    const float* x_conf  = (const float*)d_in[1];
    const float* W1      = (const float*)d_in[2];
    const float* W2      = (const float*)d_in[3];
    const float* phi1_w  = (const float*)d_in[4];
    const float* phi1_b  = (const float*)d_in[5];
    const float* phi2_w  = (const float*)d_in[6];
    const float* phi2_b  = (const float*)d_in[7];
    const float* rho_w1  = (const float*)d_in[8];
    const float* rho_b1  = (const float*)d_in[9];
    const float* rho_w2  = (const float*)d_in[10];
    const float* rho_b2  = (const float*)d_in[11];
    const float* rho_ln_w = (const float*)d_in[12];
    const float* rho_ln_b = (const float*)d_in[13];
    const int*   batch   = (const int*)d_in[14];

    float* out_enc  = (float*)d_out;
    float* out_attn = (float*)d_out + (size_t)NROWS * DDIM;

    float *q, *k;
    __nv_bfloat16 *sh1, *sl1, *sh2, *sl2, *wh, *wl;
    cudaGetSymbolAddress((void**)&q,   g_q);
    cudaGetSymbolAddress((void**)&k,   g_k);
    cudaGetSymbolAddress((void**)&sh1, g_sh1);
    cudaGetSymbolAddress((void**)&sl1, g_sl1);
    cudaGetSymbolAddress((void**)&sh2, g_sh2);
    cudaGetSymbolAddress((void**)&sl2, g_sl2);
    cudaGetSymbolAddress((void**)&wh,  g_wh);
    cudaGetSymbolAddress((void**)&wl,  g_wl);
    const size_t WSZ = (size_t)DDIM * DDIM;

    cudaFuncSetAttribute(gemm_mma, cudaFuncAttributeMaxDynamicSharedMemorySize, GM_SMEM);
    cudaFuncSetAttribute(attn_softmax16, cudaFuncAttributeMaxDynamicSharedMemorySize, AT_SMEM);
    cudaFuncSetAttribute(attn_apply16, cudaFuncAttributeMaxDynamicSharedMemorySize, AT_SMEM);

    dim3 ggrid(DDIM / 128, NROWS / 128);
    int egrid = (int)((size_t)NROWS * DDIM / 256);

    // 1: segment metadata (single kernel, reads batch directly)
    seg_kernel<<<(NROWS + 255) / 256, 256>>>(batch);
    // 2: weight splits
    w_split_all<<<4 * 65536 / 256, 256>>>(W1, W2, rho_w1, rho_w2, wh, wl);
    // 3: LN+split x_mole; 4: q projection  (position 4 = ncu-captured launch)
    ln_split_kernel<<<NROWS / 2, 256>>>(x_mole, phi1_w, phi1_b, sh1, sl1);
    gemm_mma<<<ggrid, 256, GM_SMEM>>>(sh1, sl1, wh + 0 * WSZ, wl + 0 * WSZ, q);
    // 5: LN+split x_conf; 6: k projection
    ln_split_kernel<<<NROWS / 2, 256>>>(x_conf, phi2_w, phi2_b, sh2, sl2);
    gemm_mma<<<ggrid, 256, GM_SMEM>>>(sh2, sl2, wh + 1 * WSZ, wl + 1 * WSZ, k);

    // attn zero + tiled masked softmax + tiled apply
    cudaMemsetAsync(out_attn, 0, (size_t)NROWS * NROWS * sizeof(float));
    attn_softmax16<<<NROWS / 16, 512, AT_SMEM>>>(q, k, out_attn);
    attn_apply16<<<NROWS / 16, 512, AT_SMEM>>>(out_attn, x_conf, sh1, sl1);

    // rho MLP
    gemm_mma<<<ggrid, 256, GM_SMEM>>>(sh1, sl1, wh + 2 * WSZ, wl + 2 * WSZ, q);
    epi_silu_split<<<egrid, 256>>>(q, rho_b1, sh2, sl2);
    gemm_mma<<<ggrid, 256, GM_SMEM>>>(sh2, sl2, wh + 3 * WSZ, wl + 3 * WSZ, k);
    epi_silu_inplace<<<egrid, 256>>>(k, rho_b2);

    // final LayerNorm into output
    ln_kernel<<<NROWS / 2, 256>>>(k, rho_ln_w, rho_ln_b, out_enc);
}

// round 8
// speedup vs baseline: 1.4670x; 1.4670x over previous
#include <cuda_runtime.h>
#include <cuda_bf16.h>
#include <math.h>
#include <stdint.h>

#define NROWS 8192
#define DDIM  512
#define EPS   1e-5f

// ================= PTX helpers =================
__device__ __forceinline__ uint32_t smem_u32(const void* p) {
    uint32_t a;
    asm("{ .reg .u64 t; cvta.to.shared.u64 t, %1; cvt.u32.u64 %0, t; }" : "=r"(a) : "l"(p));
    return a;
}
#define CP_ASYNC16(smem, gptr) \
    asm volatile("cp.async.cg.shared.global [%0], [%1], 16;" :: "r"(smem), "l"(gptr))
#define CP_COMMIT() asm volatile("cp.async.commit_group;" ::: "memory")
#define CP_WAIT(n)  asm volatile("cp.async.wait_group %0;" :: "n"(n) : "memory")

#define LDMX4(r, addr) \
    asm volatile("ldmatrix.sync.aligned.m8n8.x4.shared.b16 {%0,%1,%2,%3}, [%4];" \
        : "=r"((r)[0]), "=r"((r)[1]), "=r"((r)[2]), "=r"((r)[3]) : "r"(addr))

#define MMA16816(d, a, b0, b1) \
    asm volatile("mma.sync.aligned.m16n8k16.row.col.f32.bf16.bf16.f32 " \
        "{%0,%1,%2,%3}, {%4,%5,%6,%7}, {%8,%9}, {%0,%1,%2,%3};" \
        : "+f"((d)[0]), "+f"((d)[1]), "+f"((d)[2]), "+f"((d)[3]) \
        : "r"((a)[0]), "r"((a)[1]), "r"((a)[2]), "r"((a)[3]), "r"(b0), "r"(b1))

// ================= scratch =================
__device__ float g_q  [NROWS * DDIM];
__device__ float g_k  [NROWS * DDIM];
__device__ __nv_bfloat16 g_sh1[NROWS * DDIM];
__device__ __nv_bfloat16 g_sl1[NROWS * DDIM];
__device__ __nv_bfloat16 g_sh2[NROWS * DDIM];
__device__ __nv_bfloat16 g_sl2[NROWS * DDIM];
__device__ __nv_bfloat16 g_wh[4][DDIM * DDIM];
__device__ __nv_bfloat16 g_wl[4][DDIM * DDIM];
__device__ int   g_segs[NROWS];
__device__ int   g_sege[NROWS];

// ================= reductions =================
__device__ __forceinline__ float warpSum(float v) {
    #pragma unroll
    for (int o = 16; o > 0; o >>= 1) v += __shfl_xor_sync(0xffffffffu, v, o);
    return v;
}

// ================= segments =================
__global__ void seg_kernel(const int* __restrict__ p) {
    int i = blockIdx.x * blockDim.x + threadIdx.x;
    if (i >= NROWS) return;
    const int is64 = (__ldg(p + (NROWS - 1)) == 0);
    #define GETB(idx) (is64 ? __ldg(p + 2 * (idx)) : __ldg(p + (idx)))
    int v = GETB(i);
    int lo = 0, hi = NROWS;
    while (lo < hi) { int mid = (lo + hi) >> 1; if (GETB(mid) < v) lo = mid + 1; else hi = mid; }
    g_segs[i] = lo;
    lo = 0; hi = NROWS;
    while (lo < hi) { int mid = (lo + hi) >> 1; if (GETB(mid) <= v) lo = mid + 1; else hi = mid; }
    g_sege[i] = lo;
    #undef GETB
}

// ================= split helpers =================
__device__ __forceinline__ void split2(float v, __nv_bfloat16& hi, __nv_bfloat16& lo) {
    hi = __float2bfloat16(v);
    lo = __float2bfloat16(v - __bfloat162float(hi));
}

__global__ __launch_bounds__(256) void w_split_all(const float* __restrict__ W1,
                                                   const float* __restrict__ W2,
                                                   const float* __restrict__ W3,
                                                   const float* __restrict__ W4,
                                                   __nv_bfloat16* __restrict__ wh,
                                                   __nv_bfloat16* __restrict__ wl) {
    int id = blockIdx.x * 256 + threadIdx.x;
    int w = id >> 16;
    int j = id & 65535;
    const float* src = (w == 0) ? W1 : (w == 1) ? W2 : (w == 2) ? W3 : W4;
    float4 v = ((const float4*)src)[j];
    __nv_bfloat16 h0, l0, h1, l1, h2, l2, h3, l3;
    split2(v.x, h0, l0); split2(v.y, h1, l1);
    split2(v.z, h2, l2); split2(v.w, h3, l3);
    size_t base = (size_t)w * DDIM * DDIM + (size_t)j * 4;
    __nv_bfloat162* ph = (__nv_bfloat162*)(wh + base);
    __nv_bfloat162* pl = (__nv_bfloat162*)(wl + base);
    ph[0] = __nv_bfloat162(h0, h1); ph[1] = __nv_bfloat162(h2, h3);
    pl[0] = __nv_bfloat162(l0, l1); pl[1] = __nv_bfloat162(l2, l3);
}

// ================= LayerNorm: 2 rows/block, float4 =================
__global__ __launch_bounds__(256) void ln_split_kernel(const float* __restrict__ x,
                                                       const float* __restrict__ w,
                                                       const float* __restrict__ b,
                                                       __nv_bfloat16* __restrict__ sh_,
                                                       __nv_bfloat16* __restrict__ sl_) {
    __shared__ float red[2][4];
    const int half = threadIdx.x >> 7;
    const int t    = threadIdx.x & 127;
    const int lane = threadIdx.x & 31;
    const int w4   = (threadIdx.x >> 5) & 3;
    const int row  = blockIdx.x * 2 + half;
    float4 v = ((const float4*)(x + (size_t)row * DDIM))[t];
    float ps = warpSum(v.x + v.y + v.z + v.w);
    if (lane == 0) red[half][w4] = ps;
    __syncthreads();
    float mu = (red[half][0] + red[half][1] + red[half][2] + red[half][3]) * (1.0f / DDIM);
    __syncthreads();
    float dx = v.x - mu, dy = v.y - mu, dz = v.z - mu, dw = v.w - mu;
    float pv = warpSum(dx * dx + dy * dy + dz * dz + dw * dw);
    if (lane == 0) red[half][w4] = pv;
    __syncthreads();
    float var = (red[half][0] + red[half][1] + red[half][2] + red[half][3]) * (1.0f / DDIM);
    float r = rsqrtf(var + EPS);
    float4 wv = ((const float4*)w)[t];
    float4 bv = ((const float4*)b)[t];
    float y0 = dx * r * wv.x + bv.x;
    float y1 = dy * r * wv.y + bv.y;
    float y2 = dz * r * wv.z + bv.z;
    float y3 = dw * r * wv.w + bv.w;
    __nv_bfloat16 h0, l0, h1, l1, h2, l2, h3, l3;
    split2(y0, h0, l0); split2(y1, h1, l1);
    split2(y2, h2, l2); split2(y3, h3, l3);
    size_t o = (size_t)row * DDIM + t * 4;
    __nv_bfloat162* ph = (__nv_bfloat162*)(sh_ + o);
    __nv_bfloat162* pl = (__nv_bfloat162*)(sl_ + o);
    ph[0] = __nv_bfloat162(h0, h1); ph[1] = __nv_bfloat162(h2, h3);
    pl[0] = __nv_bfloat162(l0, l1); pl[1] = __nv_bfloat162(l2, l3);
}

__global__ __launch_bounds__(256) void ln_kernel(const float* __restrict__ x,
                                                 const float* __restrict__ w,
                                                 const float* __restrict__ b,
                                                 float* __restrict__ y) {
    __shared__ float red[2][4];
    const int half = threadIdx.x >> 7;
    const int t    = threadIdx.x & 127;
    const int lane = threadIdx.x & 31;
    const int w4   = (threadIdx.x >> 5) & 3;
    const int row  = blockIdx.x * 2 + half;
    float4 v = ((const float4*)(x + (size_t)row * DDIM))[t];
    float ps = warpSum(v.x + v.y + v.z + v.w);
    if (lane == 0) red[half][w4] = ps;
    __syncthreads();
    float mu = (red[half][0] + red[half][1] + red[half][2] + red[half][3]) * (1.0f / DDIM);
    __syncthreads();
    float dx = v.x - mu, dy = v.y - mu, dz = v.z - mu, dw = v.w - mu;
    float pv = warpSum(dx * dx + dy * dy + dz * dz + dw * dw);
    if (lane == 0) red[half][w4] = pv;
    __syncthreads();
    float var = (red[half][0] + red[half][1] + red[half][2] + red[half][3]) * (1.0f / DDIM);
    float r = rsqrtf(var + EPS);
    float4 wv = ((const float4*)w)[t];
    float4 bv = ((const float4*)b)[t];
    float4 o;
    o.x = dx * r * wv.x + bv.x;
    o.y = dy * r * wv.y + bv.y;
    o.z = dz * r * wv.z + bv.z;
    o.w = dw * r * wv.w + bv.w;
    ((float4*)(y + (size_t)row * DDIM))[t] = o;
}

// ================= mma.sync bf16-split GEMM (occ-1, Round-6 config) =================
// Epilogue modes: 0 = fp32 C. 1 = bias+SiLU -> bf16 split (oh/ol), no fp32.
//                 2 = bias+SiLU -> fp32 C.
#define GM_STAGE 32768
#define GM_SMEM  (3 * GM_STAGE)

__device__ __forceinline__ uint32_t swz(int row, int c16) {
    return (uint32_t)(row * 64 + ((c16 ^ ((row >> 1) & 3)) << 4));
}
__device__ __forceinline__ float silu_f(float v) { return v / (1.0f + expf(-v)); }

__global__ __launch_bounds__(256, 1) void gemm_mma(const __nv_bfloat16* __restrict__ Ah,
                                                   const __nv_bfloat16* __restrict__ Al,
                                                   const __nv_bfloat16* __restrict__ Bh,
                                                   const __nv_bfloat16* __restrict__ Bl,
                                                   float* __restrict__ C,
                                                   const float* __restrict__ bias,
                                                   __nv_bfloat16* __restrict__ oh,
                                                   __nv_bfloat16* __restrict__ ol,
                                                   int mode) {
    extern __shared__ char smem[];
    const uint32_t sbase = smem_u32(smem);
    const int tid  = threadIdx.x;
    const int lane = tid & 31;
    const int wid  = tid >> 5;
    const int wm   = wid >> 1;
    const int wn   = wid & 1;
    const int bm   = blockIdx.y * 128;
    const int bn   = blockIdx.x * 128;

    float acc[2][8][4];
    #pragma unroll
    for (int mi = 0; mi < 2; mi++)
        #pragma unroll
        for (int nj = 0; nj < 8; nj++)
            #pragma unroll
            for (int c = 0; c < 4; c++) acc[mi][nj][c] = 0.0f;

    const int id0 = tid, id1 = tid + 256;
    const int lr0 = id0 >> 2, lc0 = id0 & 3;
    const int lr1 = id1 >> 2, lc1 = id1 & 3;
    const uint32_t so0 = swz(lr0, lc0), so1 = swz(lr1, lc1);

    const int arow = (lane & 15);
    const int acol = (lane >> 4);
    const int brow = (lane & 7) + ((lane >> 4) & 1) * 8;
    const int bcol = (lane >> 3) & 1;

    #define GM_ISSUE(st, kt) do { \
        uint32_t sb_ = sbase + (st) * GM_STAGE; \
        int k0_ = (kt) * 32; \
        size_t ga0 = (size_t)(bm + lr0) * DDIM + k0_ + lc0 * 8; \
        size_t gb0 = (size_t)(bn + lr0) * DDIM + k0_ + lc0 * 8; \
        size_t ga1 = (size_t)(bm + lr1) * DDIM + k0_ + lc1 * 8; \
        size_t gb1 = (size_t)(bn + lr1) * DDIM + k0_ + lc1 * 8; \
        CP_ASYNC16(sb_ + so0,         Ah + ga0); \
        CP_ASYNC16(sb_ + 8192 + so0,  Al + ga0); \
        CP_ASYNC16(sb_ + 16384 + so0, Bh + gb0); \
        CP_ASYNC16(sb_ + 24576 + so0, Bl + gb0); \
        CP_ASYNC16(sb_ + so1,         Ah + ga1); \
        CP_ASYNC16(sb_ + 8192 + so1,  Al + ga1); \
        CP_ASYNC16(sb_ + 16384 + so1, Bh + gb1); \
        CP_ASYNC16(sb_ + 24576 + so1, Bl + gb1); \
    } while (0)

    GM_ISSUE(0, 0); CP_COMMIT();
    GM_ISSUE(1, 1); CP_COMMIT();

    for (int kt = 0; kt < 16; kt++) {
        if (kt < 14) CP_WAIT(1); else CP_WAIT(0);
        __syncthreads();
        const uint32_t sb = sbase + (kt % 3) * GM_STAGE;

        #pragma unroll
        for (int ks = 0; ks < 2; ks++) {
            uint32_t fah[2][4], fal[2][4];
            #pragma unroll
            for (int mi = 0; mi < 2; mi++) {
                uint32_t off = swz(wm * 32 + mi * 16 + arow, ks * 2 + acol);
                LDMX4(fah[mi], sb + off);
                LDMX4(fal[mi], sb + 8192 + off);
            }
            #pragma unroll
            for (int njp = 0; njp < 8; njp += 2) {
                uint32_t off = swz(wn * 64 + njp * 8 + brow, ks * 2 + bcol);
                uint32_t fbh[4], fbl[4];
                LDMX4(fbh, sb + 16384 + off);
                LDMX4(fbl, sb + 24576 + off);
                #pragma unroll
                for (int mi = 0; mi < 2; mi++) {
                    MMA16816(acc[mi][njp],     fah[mi], fbh[0], fbh[1]);
                    MMA16816(acc[mi][njp + 1], fah[mi], fbh[2], fbh[3]);
                    MMA16816(acc[mi][njp],     fah[mi], fbl[0], fbl[1]);
                    MMA16816(acc[mi][njp + 1], fah[mi], fbl[2], fbl[3]);
                    MMA16816(acc[mi][njp],     fal[mi], fbh[0], fbh[1]);
                    MMA16816(acc[mi][njp + 1], fal[mi], fbh[2], fbh[3]);
                }
            }
        }
        if (kt + 2 < 16) { GM_ISSUE((kt + 2) % 3, kt + 2); CP_COMMIT(); }
    }

    const int erow = lane >> 2;
    const int ecol = (lane & 3) * 2;
    #pragma unroll
    for (int mi = 0; mi < 2; mi++) {
        #pragma unroll
        for (int nj = 0; nj < 8; nj++) {
            int m0 = bm + wm * 32 + mi * 16 + erow;
            int n0 = bn + wn * 64 + nj * 8 + ecol;
            float2 v0 = make_float2(acc[mi][nj][0], acc[mi][nj][1]);
            float2 v1 = make_float2(acc[mi][nj][2], acc[mi][nj][3]);
            if (mode == 0) {
                *(float2*)(C + (size_t)m0 * DDIM + n0)       = v0;
                *(float2*)(C + (size_t)(m0 + 8) * DDIM + n0) = v1;
            } else {
                float2 bv = *(const float2*)(bias + n0);
                v0.x = silu_f(v0.x + bv.x); v0.y = silu_f(v0.y + bv.y);
                v1.x = silu_f(v1.x + bv.x); v1.y = silu_f(v1.y + bv.y);
                if (mode == 2) {
                    *(float2*)(C + (size_t)m0 * DDIM + n0)       = v0;
                    *(float2*)(C + (size_t)(m0 + 8) * DDIM + n0) = v1;
                } else {
                    __nv_bfloat16 h0, l0, h1, l1;
                    split2(v0.x, h0, l0); split2(v0.y, h1, l1);
                    *(__nv_bfloat162*)(oh + (size_t)m0 * DDIM + n0) = __nv_bfloat162(h0, h1);
                    *(__nv_bfloat162*)(ol + (size_t)m0 * DDIM + n0) = __nv_bfloat162(l0, l1);
                    split2(v1.x, h0, l0); split2(v1.y, h1, l1);
                    *(__nv_bfloat162*)(oh + (size_t)(m0 + 8) * DDIM + n0) = __nv_bfloat162(h0, h1);
                    *(__nv_bfloat162*)(ol + (size_t)(m0 + 8) * DDIM + n0) = __nv_bfloat162(l0, l1);
                }
            }
        }
    }
}

// ================= tiled attention =================
#define AT_TILE  32
#define AT_SMEM  (AT_TILE * DDIM * 4)

__global__ __launch_bounds__(512) void attn_softmax16(const float* __restrict__ q,
                                                      const float* __restrict__ kmat,
                                                      float* __restrict__ attn) {
    extern __shared__ float ktile[];
    const int tid = threadIdx.x, wid = tid >> 5, lane = tid & 31;
    const int i = blockIdx.x * 16 + wid;
    const int s = g_segs[i], e = g_sege[i];
    const int sb = g_segs[blockIdx.x * 16];
    const int eb = g_sege[blockIdx.x * 16 + 15];

    const float* qr = q + (size_t)i * DDIM;
    float4 qv[4];
    #pragma unroll
    for (int c = 0; c < 4; c++) qv[c] = *(const float4*)(qr + c * 128 + lane * 4);

    float* row = attn + (size_t)i * NROWS;
    float m = 0.0f;

    for (int t = sb; t < eb; t += AT_TILE) {
        const int tn = min(AT_TILE, eb - t);
        __syncthreads();
        for (int idx = tid; idx < tn * 128; idx += 512) {
            int r = idx >> 7, c = idx & 127;
            *(float4*)(ktile + r * DDIM + c * 4) = *(const float4*)(kmat + (size_t)(t + r) * DDIM + c * 4);
        }
        __syncthreads();
        const int j0 = max(s, t), j1 = min(e, t + tn);
        for (int j = j0; j < j1; j++) {
            const float* kr = ktile + (j - t) * DDIM;
            float4 k0 = *(const float4*)(kr + 0 * 128 + lane * 4);
            float4 k1 = *(const float4*)(kr + 1 * 128 + lane * 4);
            float4 k2 = *(const float4*)(kr + 2 * 128 + lane * 4);
            float4 k3 = *(const float4*)(kr + 3 * 128 + lane * 4);
            float d = qv[0].x * k0.x;
            d = fmaf(qv[0].y, k0.y, d); d = fmaf(qv[0].z, k0.z, d); d = fmaf(qv[0].w, k0.w, d);
            d = fmaf(qv[1].x, k1.x, d); d = fmaf(qv[1].y, k1.y, d); d = fmaf(qv[1].z, k1.z, d); d = fmaf(qv[1].w, k1.w, d);
            d = fmaf(qv[2].x, k2.x, d); d = fmaf(qv[2].y, k2.y, d); d = fmaf(qv[2].z, k2.z, d); d = fmaf(qv[2].w, k2.w, d);
            d = fmaf(qv[3].x, k3.x, d); d = fmaf(qv[3].y, k3.y, d); d = fmaf(qv[3].z, k3.z, d); d = fmaf(qv[3].w, k3.w, d);
            d = warpSum(d);
            if (lane == 0) row[j] = d;
            m = fmaxf(m, d);
        }
    }
    m = fmaxf(m, 0.0f);   // reference: max over dot*mask includes zeros

    float ssum = 0.0f;
    for (int j = s + lane; j < e; j += 32) {
        float ev = expf(row[j] - m);
        ssum += ev;
        row[j] = ev;
    }
    ssum = warpSum(ssum);
    float inv = 1.0f / ssum;
    for (int j = s + lane; j < e; j += 32) row[j] *= inv;
}

__global__ __launch_bounds__(512) void attn_apply16(const float* __restrict__ attn,
                                                    const float* __restrict__ xc,
                                                    __nv_bfloat16* __restrict__ sh_,
                                                    __nv_bfloat16* __restrict__ sl_) {
    extern __shared__ float xtile[];
    const int tid = threadIdx.x, wid = tid >> 5, lane = tid & 31;
    const int i = blockIdx.x * 16 + wid;
    const int s = g_segs[i], e = g_sege[i];
    const int sb = g_segs[blockIdx.x * 16];
    const int eb = g_sege[blockIdx.x * 16 + 15];
    const float* row = attn + (size_t)i * NROWS;

    float4 acc[4];
    #pragma unroll
    for (int c = 0; c < 4; c++) acc[c] = make_float4(0.f, 0.f, 0.f, 0.f);

    for (int t = sb; t < eb; t += AT_TILE) {
        const int tn = min(AT_TILE, eb - t);
        __syncthreads();
        for (int idx = tid; idx < tn * 128; idx += 512) {
            int r = idx >> 7, c = idx & 127;
            *(float4*)(xtile + r * DDIM + c * 4) = *(const float4*)(xc + (size_t)(t + r) * DDIM + c * 4);
        }
        __syncthreads();
        const int j0 = max(s, t), j1 = min(e, t + tn);
        for (int j = j0; j < j1; j++) {
            float a = __ldg(row + j);
            const float* xr = xtile + (j - t) * DDIM;
            #pragma unroll
            for (int c = 0; c < 4; c++) {
                float4 v = *(const float4*)(xr + c * 128 + lane * 4);
                acc[c].x = fmaf(a, v.x, acc[c].x);
                acc[c].y = fmaf(a, v.y, acc[c].y);
                acc[c].z = fmaf(a, v.z, acc[c].z);
                acc[c].w = fmaf(a, v.w, acc[c].w);
            }
        }
    }

    size_t base = (size_t)i * DDIM;
    #pragma unroll
    for (int c = 0; c < 4; c++) {
        size_t o = base + c * 128 + lane * 4;
        __nv_bfloat16 h, l;
        split2(acc[c].x, h, l); sh_[o + 0] = h; sl_[o + 0] = l;
        split2(acc[c].y, h, l); sh_[o + 1] = h; sl_[o + 1] = l;
        split2(acc[c].z, h, l); sh_[o + 2] = h; sl_[o + 2] = l;
        split2(acc[c].w, h, l); sh_[o + 3] = h; sl_[o + 3] = l;
    }
}

// ================= launch =================
extern "C" void kernel_launch(void* const* d_in, const int* in_sizes, int n_in,
                              void* d_out, int out_size) {
    const float* x_mole  = (const float*)d_in[0];
    const float* x_conf  = (const float*)d_in[1];
    const float* W1      = (const float*)d_in[2];
    const float* W2      = (const float*)d_in[3];
    const float* phi1_w  = (const float*)d_in[4];
    const float* phi1_b  = (const float*)d_in[5];
    const float* phi2_w  = (const float*)d_in[6];
    const float* phi2_b  = (const float*)d_in[7];
    const float* rho_w1  = (const float*)d_in[8];
    const float* rho_b1  = (const float*)d_in[9];
    const float* rho_w2  = (const float*)d_in[10];
    const float* rho_b2  = (const float*)d_in[11];
    const float* rho_ln_w = (const float*)d_in[12];
    const float* rho_ln_b = (const float*)d_in[13];
    const int*   batch   = (const int*)d_in[14];

    float* out_enc  = (float*)d_out;
    float* out_attn = (float*)d_out + (size_t)NROWS * DDIM;

    float *q, *k;
    __nv_bfloat16 *sh1, *sl1, *sh2, *sl2, *wh, *wl;
    cudaGetSymbolAddress((void**)&q,   g_q);
    cudaGetSymbolAddress((void**)&k,   g_k);
    cudaGetSymbolAddress((void**)&sh1, g_sh1);
    cudaGetSymbolAddress((void**)&sl1, g_sl1);
    cudaGetSymbolAddress((void**)&sh2, g_sh2);
    cudaGetSymbolAddress((void**)&sl2, g_sl2);
    cudaGetSymbolAddress((void**)&wh,  g_wh);
    cudaGetSymbolAddress((void**)&wl,  g_wl);
    const size_t WSZ = (size_t)DDIM * DDIM;

    cudaFuncSetAttribute(gemm_mma, cudaFuncAttributeMaxDynamicSharedMemorySize, GM_SMEM);
    cudaFuncSetAttribute(attn_softmax16, cudaFuncAttributeMaxDynamicSharedMemorySize, AT_SMEM);
    cudaFuncSetAttribute(attn_apply16, cudaFuncAttributeMaxDynamicSharedMemorySize, AT_SMEM);

    dim3 ggrid(DDIM / 128, NROWS / 128);

    // 1: segments  2: weight splits
    seg_kernel<<<(NROWS + 255) / 256, 256>>>(batch);
    w_split_all<<<4 * 65536 / 256, 256>>>(W1, W2, rho_w1, rho_w2, wh, wl);

    // 3: LN+split x_mole   4: q projection
    ln_split_kernel<<<NROWS / 2, 256>>>(x_mole, phi1_w, phi1_b, sh1, sl1);
    gemm_mma<<<ggrid, 256, GM_SMEM>>>(sh1, sl1, wh + 0 * WSZ, wl + 0 * WSZ, q,
                                      nullptr, nullptr, nullptr, 0);
    // 5: LN+split x_conf   6: k projection  (ncu-captured launch)
    ln_split_kernel<<<NROWS / 2, 256>>>(x_conf, phi2_w, phi2_b, sh2, sl2);
    gemm_mma<<<ggrid, 256, GM_SMEM>>>(sh2, sl2, wh + 1 * WSZ, wl + 1 * WSZ, k,
                                      nullptr, nullptr, nullptr, 0);

    // attn zero + tiled masked softmax + tiled apply
    cudaMemsetAsync(out_attn, 0, (size_t)NROWS * NROWS * sizeof(float));
    attn_softmax16<<<NROWS / 16, 512, AT_SMEM>>>(q, k, out_attn);
    attn_apply16<<<NROWS / 16, 512, AT_SMEM>>>(out_attn, x_conf, sh1, sl1);

    // rho MLP (epilogues fused into the GEMMs)
    gemm_mma<<<ggrid, 256, GM_SMEM>>>(sh1, sl1, wh + 2 * WSZ, wl + 2 * WSZ, nullptr,
                                      rho_b1, sh2, sl2, 1);   // bias+SiLU -> bf16 split
    gemm_mma<<<ggrid, 256, GM_SMEM>>>(sh2, sl2, wh + 3 * WSZ, wl + 3 * WSZ, k,
                                      rho_b2, nullptr, nullptr, 2); // bias+SiLU -> fp32

    // final LayerNorm into output
    ln_kernel<<<NROWS / 2, 256>>>(k, rho_ln_w, rho_ln_b, out_enc);
}

// round 9
// speedup vs baseline: 1.5609x; 1.0640x over previous
#include <cuda_runtime.h>
#include <cuda_bf16.h>
#include <math.h>
#include <stdint.h>

#define NROWS 8192
#define DDIM  512
#define EPS   1e-5f

// ================= PTX helpers =================
__device__ __forceinline__ uint32_t smem_u32(const void* p) {
    uint32_t a;
    asm("{ .reg .u64 t; cvta.to.shared.u64 t, %1; cvt.u32.u64 %0, t; }" : "=r"(a) : "l"(p));
    return a;
}
#define CP_ASYNC16(smem, gptr) \
    asm volatile("cp.async.cg.shared.global [%0], [%1], 16;" :: "r"(smem), "l"(gptr))
#define CP_COMMIT() asm volatile("cp.async.commit_group;" ::: "memory")
#define CP_WAIT(n)  asm volatile("cp.async.wait_group %0;" :: "n"(n) : "memory")

#define LDMX4(r, addr) \
    asm volatile("ldmatrix.sync.aligned.m8n8.x4.shared.b16 {%0,%1,%2,%3}, [%4];" \
        : "=r"((r)[0]), "=r"((r)[1]), "=r"((r)[2]), "=r"((r)[3]) : "r"(addr))

#define MMA16816(d, a, b0, b1) \
    asm volatile("mma.sync.aligned.m16n8k16.row.col.f32.bf16.bf16.f32 " \
        "{%0,%1,%2,%3}, {%4,%5,%6,%7}, {%8,%9}, {%0,%1,%2,%3};" \
        : "+f"((d)[0]), "+f"((d)[1]), "+f"((d)[2]), "+f"((d)[3]) \
        : "r"((a)[0]), "r"((a)[1]), "r"((a)[2]), "r"((a)[3]), "r"(b0), "r"(b1))

// ================= scratch =================
__device__ float g_q  [NROWS * DDIM];
__device__ float g_k  [NROWS * DDIM];
__device__ __nv_bfloat16 g_sh1[NROWS * DDIM];
__device__ __nv_bfloat16 g_sl1[NROWS * DDIM];
__device__ __nv_bfloat16 g_sh2[NROWS * DDIM];
__device__ __nv_bfloat16 g_sl2[NROWS * DDIM];
__device__ __nv_bfloat16 g_wh[4][DDIM * DDIM];
__device__ __nv_bfloat16 g_wl[4][DDIM * DDIM];
__device__ int   g_segs[NROWS];
__device__ int   g_sege[NROWS];

// ================= reductions =================
__device__ __forceinline__ float warpSum(float v) {
    #pragma unroll
    for (int o = 16; o > 0; o >>= 1) v += __shfl_xor_sync(0xffffffffu, v, o);
    return v;
}

// ================= segments =================
__global__ void seg_kernel(const int* __restrict__ p) {
    int i = blockIdx.x * blockDim.x + threadIdx.x;
    if (i >= NROWS) return;
    const int is64 = (__ldg(p + (NROWS - 1)) == 0);
    #define GETB(idx) (is64 ? __ldg(p + 2 * (idx)) : __ldg(p + (idx)))
    int v = GETB(i);
    int lo = 0, hi = NROWS;
    while (lo < hi) { int mid = (lo + hi) >> 1; if (GETB(mid) < v) lo = mid + 1; else hi = mid; }
    g_segs[i] = lo;
    lo = 0; hi = NROWS;
    while (lo < hi) { int mid = (lo + hi) >> 1; if (GETB(mid) <= v) lo = mid + 1; else hi = mid; }
    g_sege[i] = lo;
    #undef GETB
}

// ================= split helpers =================
__device__ __forceinline__ void split2(float v, __nv_bfloat16& hi, __nv_bfloat16& lo) {
    hi = __float2bfloat16(v);
    lo = __float2bfloat16(v - __bfloat162float(hi));
}

__global__ __launch_bounds__(256) void w_split_all(const float* __restrict__ W1,
                                                   const float* __restrict__ W2,
                                                   const float* __restrict__ W3,
                                                   const float* __restrict__ W4,
                                                   __nv_bfloat16* __restrict__ wh,
                                                   __nv_bfloat16* __restrict__ wl) {
    int id = blockIdx.x * 256 + threadIdx.x;
    int w = id >> 16;
    int j = id & 65535;
    const float* src = (w == 0) ? W1 : (w == 1) ? W2 : (w == 2) ? W3 : W4;
    float4 v = ((const float4*)src)[j];
    __nv_bfloat16 h0, l0, h1, l1, h2, l2, h3, l3;
    split2(v.x, h0, l0); split2(v.y, h1, l1);
    split2(v.z, h2, l2); split2(v.w, h3, l3);
    size_t base = (size_t)w * DDIM * DDIM + (size_t)j * 4;
    __nv_bfloat162* ph = (__nv_bfloat162*)(wh + base);
    __nv_bfloat162* pl = (__nv_bfloat162*)(wl + base);
    ph[0] = __nv_bfloat162(h0, h1); ph[1] = __nv_bfloat162(h2, h3);
    pl[0] = __nv_bfloat162(l0, l1); pl[1] = __nv_bfloat162(l2, l3);
}

// ================= LayerNorm: 2 rows/block, float4 =================
__global__ __launch_bounds__(256) void ln_split_kernel(const float* __restrict__ x,
                                                       const float* __restrict__ w,
                                                       const float* __restrict__ b,
                                                       __nv_bfloat16* __restrict__ sh_,
                                                       __nv_bfloat16* __restrict__ sl_) {
    __shared__ float red[2][4];
    const int half = threadIdx.x >> 7;
    const int t    = threadIdx.x & 127;
    const int lane = threadIdx.x & 31;
    const int w4   = (threadIdx.x >> 5) & 3;
    const int row  = blockIdx.x * 2 + half;
    float4 v = ((const float4*)(x + (size_t)row * DDIM))[t];
    float ps = warpSum(v.x + v.y + v.z + v.w);
    if (lane == 0) red[half][w4] = ps;
    __syncthreads();
    float mu = (red[half][0] + red[half][1] + red[half][2] + red[half][3]) * (1.0f / DDIM);
    __syncthreads();
    float dx = v.x - mu, dy = v.y - mu, dz = v.z - mu, dw = v.w - mu;
    float pv = warpSum(dx * dx + dy * dy + dz * dz + dw * dw);
    if (lane == 0) red[half][w4] = pv;
    __syncthreads();
    float var = (red[half][0] + red[half][1] + red[half][2] + red[half][3]) * (1.0f / DDIM);
    float r = rsqrtf(var + EPS);
    float4 wv = ((const float4*)w)[t];
    float4 bv = ((const float4*)b)[t];
    float y0 = dx * r * wv.x + bv.x;
    float y1 = dy * r * wv.y + bv.y;
    float y2 = dz * r * wv.z + bv.z;
    float y3 = dw * r * wv.w + bv.w;
    __nv_bfloat16 h0, l0, h1, l1, h2, l2, h3, l3;
    split2(y0, h0, l0); split2(y1, h1, l1);
    split2(y2, h2, l2); split2(y3, h3, l3);
    size_t o = (size_t)row * DDIM + t * 4;
    __nv_bfloat162* ph = (__nv_bfloat162*)(sh_ + o);
    __nv_bfloat162* pl = (__nv_bfloat162*)(sl_ + o);
    ph[0] = __nv_bfloat162(h0, h1); ph[1] = __nv_bfloat162(h2, h3);
    pl[0] = __nv_bfloat162(l0, l1); pl[1] = __nv_bfloat162(l2, l3);
}

__global__ __launch_bounds__(256) void ln_kernel(const float* __restrict__ x,
                                                 const float* __restrict__ w,
                                                 const float* __restrict__ b,
                                                 float* __restrict__ y) {
    __shared__ float red[2][4];
    const int half = threadIdx.x >> 7;
    const int t    = threadIdx.x & 127;
    const int lane = threadIdx.x & 31;
    const int w4   = (threadIdx.x >> 5) & 3;
    const int row  = blockIdx.x * 2 + half;
    float4 v = ((const float4*)(x + (size_t)row * DDIM))[t];
    float ps = warpSum(v.x + v.y + v.z + v.w);
    if (lane == 0) red[half][w4] = ps;
    __syncthreads();
    float mu = (red[half][0] + red[half][1] + red[half][2] + red[half][3]) * (1.0f / DDIM);
    __syncthreads();
    float dx = v.x - mu, dy = v.y - mu, dz = v.z - mu, dw = v.w - mu;
    float pv = warpSum(dx * dx + dy * dy + dz * dz + dw * dw);
    if (lane == 0) red[half][w4] = pv;
    __syncthreads();
    float var = (red[half][0] + red[half][1] + red[half][2] + red[half][3]) * (1.0f / DDIM);
    float r = rsqrtf(var + EPS);
    float4 wv = ((const float4*)w)[t];
    float4 bv = ((const float4*)b)[t];
    float4 o;
    o.x = dx * r * wv.x + bv.x;
    o.y = dy * r * wv.y + bv.y;
    o.z = dz * r * wv.z + bv.z;
    o.w = dw * r * wv.w + bv.w;
    ((float4*)(y + (size_t)row * DDIM))[t] = o;
}

// ================= mma.sync bf16-split GEMM: 512 thr, 16 warps (4m x 4n) =================
// BM=128, BN=128, BK=32. Warp tile 32x32 -> acc 32 regs/thread, 4 warps/SMSP
// for tensor-latency hiding. 3-stage cp.async pipeline, swizzled 64B rows.
// Epilogue modes: 0 = fp32 C. 1 = bias+SiLU -> bf16 split. 2 = bias+SiLU -> fp32.
#define GM_STAGE 32768
#define GM_SMEM  (3 * GM_STAGE)

__device__ __forceinline__ uint32_t swz(int row, int c16) {
    return (uint32_t)(row * 64 + ((c16 ^ ((row >> 1) & 3)) << 4));
}
__device__ __forceinline__ float silu_f(float v) { return v / (1.0f + expf(-v)); }

__global__ __launch_bounds__(512, 1) void gemm_mma(const __nv_bfloat16* __restrict__ Ah,
                                                   const __nv_bfloat16* __restrict__ Al,
                                                   const __nv_bfloat16* __restrict__ Bh,
                                                   const __nv_bfloat16* __restrict__ Bl,
                                                   float* __restrict__ C,
                                                   const float* __restrict__ bias,
                                                   __nv_bfloat16* __restrict__ oh,
                                                   __nv_bfloat16* __restrict__ ol,
                                                   int mode) {
    extern __shared__ char smem[];
    const uint32_t sbase = smem_u32(smem);
    const int tid  = threadIdx.x;
    const int lane = tid & 31;
    const int wid  = tid >> 5;       // 0..15
    const int wm   = wid >> 2;       // 0..3 -> 32 rows
    const int wn   = wid & 3;        // 0..3 -> 32 cols
    const int bm   = blockIdx.y * 128;
    const int bn   = blockIdx.x * 128;

    float acc[2][4][4];
    #pragma unroll
    for (int mi = 0; mi < 2; mi++)
        #pragma unroll
        for (int nj = 0; nj < 4; nj++)
            #pragma unroll
            for (int c = 0; c < 4; c++) acc[mi][nj][c] = 0.0f;

    // loads: 512 threads x 1 chunk of 16B per tile per stage (128 rows x 4 chunks)
    const int lr0 = tid >> 2, lc0 = tid & 3;
    const uint32_t so0 = swz(lr0, lc0);

    const int arow = (lane & 15);
    const int acol = (lane >> 4);
    const int brow = (lane & 7) + ((lane >> 4) & 1) * 8;
    const int bcol = (lane >> 3) & 1;

    #define GM_ISSUE(st, kt) do { \
        uint32_t sb_ = sbase + (st) * GM_STAGE; \
        int k0_ = (kt) * 32; \
        size_t ga0 = (size_t)(bm + lr0) * DDIM + k0_ + lc0 * 8; \
        size_t gb0 = (size_t)(bn + lr0) * DDIM + k0_ + lc0 * 8; \
        CP_ASYNC16(sb_ + so0,         Ah + ga0); \
        CP_ASYNC16(sb_ + 8192 + so0,  Al + ga0); \
        CP_ASYNC16(sb_ + 16384 + so0, Bh + gb0); \
        CP_ASYNC16(sb_ + 24576 + so0, Bl + gb0); \
    } while (0)

    GM_ISSUE(0, 0); CP_COMMIT();
    GM_ISSUE(1, 1); CP_COMMIT();

    for (int kt = 0; kt < 16; kt++) {
        if (kt < 14) CP_WAIT(1); else CP_WAIT(0);
        __syncthreads();
        const uint32_t sb = sbase + (kt % 3) * GM_STAGE;

        #pragma unroll
        for (int ks = 0; ks < 2; ks++) {
            uint32_t fah[2][4], fal[2][4];
            #pragma unroll
            for (int mi = 0; mi < 2; mi++) {
                uint32_t off = swz(wm * 32 + mi * 16 + arow, ks * 2 + acol);
                LDMX4(fah[mi], sb + off);
                LDMX4(fal[mi], sb + 8192 + off);
            }
            #pragma unroll
            for (int njp = 0; njp < 4; njp += 2) {
                uint32_t off = swz(wn * 32 + njp * 8 + brow, ks * 2 + bcol);
                uint32_t fbh[4], fbl[4];
                LDMX4(fbh, sb + 16384 + off);
                LDMX4(fbl, sb + 24576 + off);
                #pragma unroll
                for (int mi = 0; mi < 2; mi++) {
                    MMA16816(acc[mi][njp],     fah[mi], fbh[0], fbh[1]);
                    MMA16816(acc[mi][njp + 1], fah[mi], fbh[2], fbh[3]);
                    MMA16816(acc[mi][njp],     fah[mi], fbl[0], fbl[1]);
                    MMA16816(acc[mi][njp + 1], fah[mi], fbl[2], fbl[3]);
                    MMA16816(acc[mi][njp],     fal[mi], fbh[0], fbh[1]);
                    MMA16816(acc[mi][njp + 1], fal[mi], fbh[2], fbh[3]);
                }
            }
        }
        if (kt + 2 < 16) { GM_ISSUE((kt + 2) % 3, kt + 2); CP_COMMIT(); }
    }

    const int erow = lane >> 2;
    const int ecol = (lane & 3) * 2;
    #pragma unroll
    for (int mi = 0; mi < 2; mi++) {
        #pragma unroll
        for (int nj = 0; nj < 4; nj++) {
            int m0 = bm + wm * 32 + mi * 16 + erow;
            int n0 = bn + wn * 32 + nj * 8 + ecol;
            float2 v0 = make_float2(acc[mi][nj][0], acc[mi][nj][1]);
            float2 v1 = make_float2(acc[mi][nj][2], acc[mi][nj][3]);
            if (mode == 0) {
                *(float2*)(C + (size_t)m0 * DDIM + n0)       = v0;
                *(float2*)(C + (size_t)(m0 + 8) * DDIM + n0) = v1;
            } else {
                float2 bv = *(const float2*)(bias + n0);
                v0.x = silu_f(v0.x + bv.x); v0.y = silu_f(v0.y + bv.y);
                v1.x = silu_f(v1.x + bv.x); v1.y = silu_f(v1.y + bv.y);
                if (mode == 2) {
                    *(float2*)(C + (size_t)m0 * DDIM + n0)       = v0;
                    *(float2*)(C + (size_t)(m0 + 8) * DDIM + n0) = v1;
                } else {
                    __nv_bfloat16 h0, l0, h1, l1;
                    split2(v0.x, h0, l0); split2(v0.y, h1, l1);
                    *(__nv_bfloat162*)(oh + (size_t)m0 * DDIM + n0) = __nv_bfloat162(h0, h1);
                    *(__nv_bfloat162*)(ol + (size_t)m0 * DDIM + n0) = __nv_bfloat162(l0, l1);
                    split2(v1.x, h0, l0); split2(v1.y, h1, l1);
                    *(__nv_bfloat162*)(oh + (size_t)(m0 + 8) * DDIM + n0) = __nv_bfloat162(h0, h1);
                    *(__nv_bfloat162*)(ol + (size_t)(m0 + 8) * DDIM + n0) = __nv_bfloat162(l0, l1);
                }
            }
        }
    }
}

// ================= tiled attention =================
// softmax also zero-fills the out-of-segment part of each row (replaces the
// 256MB cudaMemsetAsync; stores issued BEFORE compute so they drain behind it).
#define AT_TILE  32
#define AT_SMEM  (AT_TILE * DDIM * 4)

__global__ __launch_bounds__(512) void attn_softmax16(const float* __restrict__ q,
                                                      const float* __restrict__ kmat,
                                                      float* __restrict__ attn) {
    extern __shared__ float ktile[];
    const int tid = threadIdx.x, wid = tid >> 5, lane = tid & 31;
    const int i = blockIdx.x * 16 + wid;
    const int s = g_segs[i], e = g_sege[i];
    const int sb = g_segs[blockIdx.x * 16];
    const int eb = g_sege[blockIdx.x * 16 + 15];

    float* row = attn + (size_t)i * NROWS;

    // zero-fill outside [s, e) first -- pure stores, overlap with dot compute
    for (int j = lane; j < s; j += 32)          row[j] = 0.0f;
    for (int j = e + lane; j < NROWS; j += 32)  row[j] = 0.0f;

    const float* qr = q + (size_t)i * DDIM;
    float4 qv[4];
    #pragma unroll
    for (int c = 0; c < 4; c++) qv[c] = *(const float4*)(qr + c * 128 + lane * 4);

    float m = 0.0f;
    for (int t = sb; t < eb; t += AT_TILE) {
        const int tn = min(AT_TILE, eb - t);
        __syncthreads();
        for (int idx = tid; idx < tn * 128; idx += 512) {
            int r = idx >> 7, c = idx & 127;
            *(float4*)(ktile + r * DDIM + c * 4) = *(const float4*)(kmat + (size_t)(t + r) * DDIM + c * 4);
        }
        __syncthreads();
        const int j0 = max(s, t), j1 = min(e, t + tn);
        for (int j = j0; j < j1; j++) {
            const float* kr = ktile + (j - t) * DDIM;
            float4 k0 = *(const float4*)(kr + 0 * 128 + lane * 4);
            float4 k1 = *(const float4*)(kr + 1 * 128 + lane * 4);
            float4 k2 = *(const float4*)(kr + 2 * 128 + lane * 4);
            float4 k3 = *(const float4*)(kr + 3 * 128 + lane * 4);
            float d = qv[0].x * k0.x;
            d = fmaf(qv[0].y, k0.y, d); d = fmaf(qv[0].z, k0.z, d); d = fmaf(qv[0].w, k0.w, d);
            d = fmaf(qv[1].x, k1.x, d); d = fmaf(qv[1].y, k1.y, d); d = fmaf(qv[1].z, k1.z, d); d = fmaf(qv[1].w, k1.w, d);
            d = fmaf(qv[2].x, k2.x, d); d = fmaf(qv[2].y, k2.y, d); d = fmaf(qv[2].z, k2.z, d); d = fmaf(qv[2].w, k2.w, d);
            d = fmaf(qv[3].x, k3.x, d); d = fmaf(qv[3].y, k3.y, d); d = fmaf(qv[3].z, k3.z, d); d = fmaf(qv[3].w, k3.w, d);
            d = warpSum(d);
            if (lane == 0) row[j] = d;
            m = fmaxf(m, d);
        }
    }
    m = fmaxf(m, 0.0f);   // reference: max over dot*mask includes zeros

    float ssum = 0.0f;
    for (int j = s + lane; j < e; j += 32) {
        float ev = expf(row[j] - m);
        ssum += ev;
        row[j] = ev;
    }
    ssum = warpSum(ssum);
    float inv = 1.0f / ssum;
    for (int j = s + lane; j < e; j += 32) row[j] *= inv;
}

__global__ __launch_bounds__(512) void attn_apply16(const float* __restrict__ attn,
                                                    const float* __restrict__ xc,
                                                    __nv_bfloat16* __restrict__ sh_,
                                                    __nv_bfloat16* __restrict__ sl_) {
    extern __shared__ float xtile[];
    const int tid = threadIdx.x, wid = tid >> 5, lane = tid & 31;
    const int i = blockIdx.x * 16 + wid;
    const int s = g_segs[i], e = g_sege[i];
    const int sb = g_segs[blockIdx.x * 16];
    const int eb = g_sege[blockIdx.x * 16 + 15];
    const float* row = attn + (size_t)i * NROWS;

    float4 acc[4];
    #pragma unroll
    for (int c = 0; c < 4; c++) acc[c] = make_float4(0.f, 0.f, 0.f, 0.f);

    for (int t = sb; t < eb; t += AT_TILE) {
        const int tn = min(AT_TILE, eb - t);
        __syncthreads();
        for (int idx = tid; idx < tn * 128; idx += 512) {
            int r = idx >> 7, c = idx & 127;
            *(float4*)(xtile + r * DDIM + c * 4) = *(const float4*)(xc + (size_t)(t + r) * DDIM + c * 4);
        }
        __syncthreads();
        const int j0 = max(s, t), j1 = min(e, t + tn);
        for (int j = j0; j < j1; j++) {
            float a = __ldg(row + j);
            const float* xr = xtile + (j - t) * DDIM;
            #pragma unroll
            for (int c = 0; c < 4; c++) {
                float4 v = *(const float4*)(xr + c * 128 + lane * 4);
                acc[c].x = fmaf(a, v.x, acc[c].x);
                acc[c].y = fmaf(a, v.y, acc[c].y);
                acc[c].z = fmaf(a, v.z, acc[c].z);
                acc[c].w = fmaf(a, v.w, acc[c].w);
            }
        }
    }

    size_t base = (size_t)i * DDIM;
    #pragma unroll
    for (int c = 0; c < 4; c++) {
        size_t o = base + c * 128 + lane * 4;
        __nv_bfloat16 h, l;
        split2(acc[c].x, h, l); sh_[o + 0] = h; sl_[o + 0] = l;
        split2(acc[c].y, h, l); sh_[o + 1] = h; sl_[o + 1] = l;
        split2(acc[c].z, h, l); sh_[o + 2] = h; sl_[o + 2] = l;
        split2(acc[c].w, h, l); sh_[o + 3] = h; sl_[o + 3] = l;
    }
}

// ================= launch =================
extern "C" void kernel_launch(void* const* d_in, const int* in_sizes, int n_in,
                              void* d_out, int out_size) {
    const float* x_mole  = (const float*)d_in[0];
    const float* x_conf  = (const float*)d_in[1];
    const float* W1      = (const float*)d_in[2];
    const float* W2      = (const float*)d_in[3];
    const float* phi1_w  = (const float*)d_in[4];
    const float* phi1_b  = (const float*)d_in[5];
    const float* phi2_w  = (const float*)d_in[6];
    const float* phi2_b  = (const float*)d_in[7];
    const float* rho_w1  = (const float*)d_in[8];
    const float* rho_b1  = (const float*)d_in[9];
    const float* rho_w2  = (const float*)d_in[10];
    const float* rho_b2  = (const float*)d_in[11];
    const float* rho_ln_w = (const float*)d_in[12];
    const float* rho_ln_b = (const float*)d_in[13];
    const int*   batch   = (const int*)d_in[14];

    float* out_enc  = (float*)d_out;
    float* out_attn = (float*)d_out + (size_t)NROWS * DDIM;

    float *q, *k;
    __nv_bfloat16 *sh1, *sl1, *sh2, *sl2, *wh, *wl;
    cudaGetSymbolAddress((void**)&q,   g_q);
    cudaGetSymbolAddress((void**)&k,   g_k);
    cudaGetSymbolAddress((void**)&sh1, g_sh1);
    cudaGetSymbolAddress((void**)&sl1, g_sl1);
    cudaGetSymbolAddress((void**)&sh2, g_sh2);
    cudaGetSymbolAddress((void**)&sl2, g_sl2);
    cudaGetSymbolAddress((void**)&wh,  g_wh);
    cudaGetSymbolAddress((void**)&wl,  g_wl);
    const size_t WSZ = (size_t)DDIM * DDIM;

    cudaFuncSetAttribute(gemm_mma, cudaFuncAttributeMaxDynamicSharedMemorySize, GM_SMEM);
    cudaFuncSetAttribute(attn_softmax16, cudaFuncAttributeMaxDynamicSharedMemorySize, AT_SMEM);
    cudaFuncSetAttribute(attn_apply16, cudaFuncAttributeMaxDynamicSharedMemorySize, AT_SMEM);

    dim3 ggrid(DDIM / 128, NROWS / 128);

    // 1: segments  2: weight splits
    seg_kernel<<<(NROWS + 255) / 256, 256>>>(batch);
    w_split_all<<<4 * 65536 / 256, 256>>>(W1, W2, rho_w1, rho_w2, wh, wl);

    // 3: LN+split x_mole   4: q projection
    ln_split_kernel<<<NROWS / 2, 256>>>(x_mole, phi1_w, phi1_b, sh1, sl1);
    gemm_mma<<<ggrid, 512, GM_SMEM>>>(sh1, sl1, wh + 0 * WSZ, wl + 0 * WSZ, q,
                                      nullptr, nullptr, nullptr, 0);
    // 5: LN+split x_conf   6: k projection  (ncu-captured launch)
    ln_split_kernel<<<NROWS / 2, 256>>>(x_conf, phi2_w, phi2_b, sh2, sl2);
    gemm_mma<<<ggrid, 512, GM_SMEM>>>(sh2, sl2, wh + 1 * WSZ, wl + 1 * WSZ, k,
                                      nullptr, nullptr, nullptr, 0);

    // tiled masked softmax (with fused zero-fill) + tiled apply
    attn_softmax16<<<NROWS / 16, 512, AT_SMEM>>>(q, k, out_attn);
    attn_apply16<<<NROWS / 16, 512, AT_SMEM>>>(out_attn, x_conf, sh1, sl1);

    // rho MLP (epilogues fused into the GEMMs)
    gemm_mma<<<ggrid, 512, GM_SMEM>>>(sh1, sl1, wh + 2 * WSZ, wl + 2 * WSZ, nullptr,
                                      rho_b1, sh2, sl2, 1);   // bias+SiLU -> bf16 split
    gemm_mma<<<ggrid, 512, GM_SMEM>>>(sh2, sl2, wh + 3 * WSZ, wl + 3 * WSZ, k,
                                      rho_b2, nullptr, nullptr, 2); // bias+SiLU -> fp32

    // final LayerNorm into output
    ln_kernel<<<NROWS / 2, 256>>>(k, rho_ln_w, rho_ln_b, out_enc);
}